// round 5
// baseline (speedup 1.0000x reference)
#include <cuda_runtime.h>
#include <math.h>

#define MASK  0x7FFFFu
#define P1    2654435761u
#define P2    805459861u
#define NPTS_MAX (1 << 20)
#define NB   262144        // 64^3 Morton buckets

typedef unsigned long long ull;

struct Params {
    float icell[16];   // res/2  (u = (x+1) * icell)
    float resm1[16];   // res-1 as float (clamp ceiling)
};

// ---------------- scratch (static device arrays; no runtime alloc) ----------
__device__ unsigned d_hist[NB];
__device__ unsigned d_offs[NB];
__device__ float4   d_xs[NPTS_MAX];

// ---------------- helpers ---------------------------------------------------
__device__ __forceinline__ ull pk2(float a, float b) {
    ull r;
    asm("mov.b64 %0, {%1, %2};" : "=l"(r) : "f"(a), "f"(b));
    return r;
}

// packed lerp: a + t*(b-a) on two f32 lanes (sm_100+ f32x2 ops)
__device__ __forceinline__ ull lerp2(ull a, ull b, ull t) {
    ull d, r;
    asm("sub.rn.f32x2 %0, %1, %2;" : "=l"(d) : "l"(b), "l"(a));
    asm("fma.rn.f32x2 %0, %1, %2, %3;" : "=l"(r) : "l"(t), "l"(d), "l"(a));
    return r;
}

__device__ __forceinline__ unsigned expand_bits(unsigned v) {
    v &= 0x3FFu;
    v = (v | (v << 16)) & 0x030000FFu;
    v = (v | (v << 8))  & 0x0300F00Fu;
    v = (v | (v << 4))  & 0x030C30C3u;
    v = (v | (v << 2))  & 0x09249249u;
    return v;
}

__device__ __forceinline__ unsigned bucket_key(float px, float py, float pz) {
    const float s = 32.0f;   // [-1,1] -> [0,64)
    int ix = min(max(__float2int_rd(fmaf(px, s, s)), 0), 63);
    int iy = min(max(__float2int_rd(fmaf(py, s, s)), 0), 63);
    int iz = min(max(__float2int_rd(fmaf(pz, s, s)), 0), 63);
    return expand_bits((unsigned)ix) | (expand_bits((unsigned)iy) << 1)
         | (expand_bits((unsigned)iz) << 2);
}

// ---------------- sorting kernels -------------------------------------------
__global__ void k_zero() {
    d_hist[blockIdx.x * 256u + threadIdx.x] = 0u;
}

__global__ void k_hist(const float* __restrict__ x, int n) {
    int p = blockIdx.x * 256 + threadIdx.x;
    if (p >= n) return;
    float px = x[3 * p], py = x[3 * p + 1], pz = x[3 * p + 2];
    atomicAdd(&d_hist[bucket_key(px, py, pz)], 1u);
}

__global__ void k_scan() {   // single block, 1024 threads, chunk = NB/1024 = 256
    __shared__ unsigned part[1024];
    const int CH = NB / 1024;
    int tid = threadIdx.x;
    unsigned base = tid * CH;
    unsigned s = 0;
    for (int i = 0; i < CH; i++) s += d_hist[base + i];
    part[tid] = s;
    __syncthreads();
    if (tid == 0) {
        unsigned acc = 0;
        for (int i = 0; i < 1024; i++) { unsigned t = part[i]; part[i] = acc; acc += t; }
    }
    __syncthreads();
    unsigned acc = part[tid];
    for (int i = 0; i < CH; i++) {
        unsigned t = d_hist[base + i];
        d_offs[base + i] = acc;
        acc += t;
    }
}

__global__ void k_scatter(const float* __restrict__ x, int n) {
    int p = blockIdx.x * 256 + threadIdx.x;
    if (p >= n) return;
    float px = x[3 * p], py = x[3 * p + 1], pz = x[3 * p + 2];
    unsigned dst = atomicAdd(&d_offs[bucket_key(px, py, pz)], 1u);
    d_xs[dst] = make_float4(px, py, pz, __uint_as_float((unsigned)p));
}

// ---------------- main kernel ------------------------------------------------
__global__ __launch_bounds__(256) void hash_embed_kernel(
    const ull* __restrict__ tbl,    // tables as (level<<19) float2 entries
    float* __restrict__ out,
    int npts,
    Params prm)
{
    // small staging: only 4 levels (8 floats) per point at a time.
    // total smem = 8*32*9*4 + 8*32*4 = 10.2 KB/block -> L1D stays ~180+ KB.
    __shared__ float    stage[8][32][9];
    __shared__ unsigned idxs[8][32];

    unsigned i = blockIdx.x * 256u + threadIdx.x;
    int w   = threadIdx.x >> 5;
    int lid = threadIdx.x & 31;

    unsigned p = 0xFFFFFFFFu;
    float px = 0.f, py = 0.f, pz = 0.f;
    if (i < (unsigned)npts) {
        float4 v = d_xs[i];
        px = v.x; py = v.y; pz = v.z;
        p = __float_as_uint(v.w);
    }
    idxs[w][lid] = p;

#pragma unroll
    for (int l = 0; l < 16; l++) {
        const float ic  = prm.icell[l];
        const float rm1 = prm.resm1[l];

        float ux = fmaf(px, ic, ic);
        float uy = fmaf(py, ic, ic);
        float uz = fmaf(pz, ic, ic);
        float fx = fminf(floorf(ux), rm1);
        float fy = fminf(floorf(uy), rm1);
        float fz = fminf(floorf(uz), rm1);
        float tx = ux - fx;
        float ty = uy - fy;
        float tz = uz - fz;

        unsigned ix0 = (unsigned)fx;
        unsigned iy0 = (unsigned)fy;
        unsigned iz0 = (unsigned)fz;
        unsigned hy0 = iy0 * P1;
        unsigned hy1 = hy0 + P1;
        unsigned hz0 = iz0 * P2;
        unsigned hz1 = hz0 + P2;

        unsigned r00 = hy0 ^ hz0;
        unsigned r10 = hy1 ^ hz0;
        unsigned r01 = hy0 ^ hz1;
        unsigned r11 = hy1 ^ hz1;

        unsigned h00 = (ix0 ^ r00) & MASK;
        unsigned h10 = (ix0 ^ r10) & MASK;
        unsigned h01 = (ix0 ^ r01) & MASK;
        unsigned h11 = (ix0 ^ r11) & MASK;

        const ull* tl = tbl + ((unsigned)l << 19);
        const ulonglong2* tp = (const ulonglong2*)tl;

        // one 16B load covers the (ix0, ix0^1) vertex pair; everything
        // caches in L1 (sorted points give warp/block-local reuse)
        ulonglong2 q00 = __ldg(tp + (h00 >> 1));
        ulonglong2 q10 = __ldg(tp + (h10 >> 1));
        ulonglong2 q01 = __ldg(tp + (h01 >> 1));
        ulonglong2 q11 = __ldg(tp + (h11 >> 1));

        ull e000 = (h00 & 1) ? q00.y : q00.x;
        ull e010 = (h10 & 1) ? q10.y : q10.x;
        ull e001 = (h01 & 1) ? q01.y : q01.x;
        ull e011 = (h11 & 1) ? q11.y : q11.x;

        ull e100, e110, e101, e111;
        if (ix0 & 1) {
            unsigned ix1 = ix0 + 1u;
            e100 = __ldg(tl + ((ix1 ^ r00) & MASK));
            e110 = __ldg(tl + ((ix1 ^ r10) & MASK));
            e101 = __ldg(tl + ((ix1 ^ r01) & MASK));
            e111 = __ldg(tl + ((ix1 ^ r11) & MASK));
        } else {
            e100 = (h00 & 1) ? q00.x : q00.y;
            e110 = (h10 & 1) ? q10.x : q10.y;
            e101 = (h01 & 1) ? q01.x : q01.y;
            e111 = (h11 & 1) ? q11.x : q11.y;
        }

        ull t2x = pk2(tx, tx);
        ull t2y = pk2(ty, ty);
        ull t2z = pk2(tz, tz);

        ull a0 = lerp2(e000, e100, t2x);
        ull a1 = lerp2(e010, e110, t2x);
        ull a2 = lerp2(e001, e101, t2x);
        ull a3 = lerp2(e011, e111, t2x);
        ull b0 = lerp2(a0, a1, t2y);
        ull b1 = lerp2(a2, a3, t2y);
        ull r  = lerp2(b0, b1, t2z);

        float2 rf = *reinterpret_cast<float2*>(&r);
        int sl = l & 3;
        stage[w][lid][2 * sl + 0] = rf.x;
        stage[w][lid][2 * sl + 1] = rf.y;

        if (sl == 3) {
            int g = l >> 2;
            __syncwarp();
            // flush 4 points per instruction: lane = (point-sub)*8 + feature
            int f  = lid & 7;
            int js = lid >> 3;
#pragma unroll
            for (int jq = 0; jq < 8; jq++) {
                int j = jq * 4 + js;
                unsigned pj = idxs[w][j];
                if (pj != 0xFFFFFFFFu)
                    __stcs(out + (ull)pj * 32u + g * 8 + f, stage[w][j][f]);
            }
            __syncwarp();
        }
    }
}

// ---------------- launch ------------------------------------------------------
extern "C" void kernel_launch(void* const* d_in, const int* in_sizes, int n_in,
                              void* d_out, int out_size) {
    int xi = 0, ti = 1;
    if (n_in >= 2 && in_sizes[0] > in_sizes[1]) { xi = 1; ti = 0; }

    const float* x = (const float*)d_in[xi];
    const ull* tbl = (const ull*)d_in[ti];
    float* out = (float*)d_out;

    Params prm;
    double factor = exp((log(512.0) - log(16.0)) / 15.0);
    for (int i = 0; i < 16; i++) {
        double r = floor(16.0 * pow(factor, (double)i));
        prm.icell[i] = (float)(r * 0.5);
        prm.resm1[i] = (float)(r - 1.0);
    }

    int npts = in_sizes[xi] / 3;
    int pb = (npts + 255) / 256;

    k_zero<<<NB / 256, 256>>>();
    k_hist<<<pb, 256>>>(x, npts);
    k_scan<<<1, 1024>>>();
    k_scatter<<<pb, 256>>>(x, npts);
    hash_embed_kernel<<<pb, 256>>>(tbl, out, npts, prm);
}

// round 6
// speedup vs baseline: 1.0145x; 1.0145x over previous
#include <cuda_runtime.h>
#include <math.h>

#define MASK  0x7FFFFu
#define P1    2654435761u
#define P2    805459861u
#define NPTS_MAX (1 << 20)
#define NB   262144        // 64^3 Morton buckets

typedef unsigned long long ull;

struct Params {
    float icell[16];   // res/2  (u = (x+1) * icell)
    float resm1[16];   // res-1 as float (clamp ceiling)
};

// ---------------- scratch (static device arrays; no runtime alloc) ----------
__device__ unsigned d_hist[NB];
__device__ unsigned d_offs[NB];
__device__ float4   d_xs[NPTS_MAX];

// ---------------- helpers ---------------------------------------------------
__device__ __forceinline__ ull pk2(float a, float b) {
    ull r;
    asm("mov.b64 %0, {%1, %2};" : "=l"(r) : "f"(a), "f"(b));
    return r;
}

// packed lerp: a + t*(b-a) on two f32 lanes (sm_100+ f32x2 ops)
__device__ __forceinline__ ull lerp2(ull a, ull b, ull t) {
    ull d, r;
    asm("sub.rn.f32x2 %0, %1, %2;" : "=l"(d) : "l"(b), "l"(a));
    asm("fma.rn.f32x2 %0, %1, %2, %3;" : "=l"(r) : "l"(t), "l"(d), "l"(a));
    return r;
}

__device__ __forceinline__ unsigned expand_bits(unsigned v) {
    v &= 0x3FFu;
    v = (v | (v << 16)) & 0x030000FFu;
    v = (v | (v << 8))  & 0x0300F00Fu;
    v = (v | (v << 4))  & 0x030C30C3u;
    v = (v | (v << 2))  & 0x09249249u;
    return v;
}

__device__ __forceinline__ unsigned bucket_key(float px, float py, float pz) {
    const float s = 32.0f;   // [-1,1] -> [0,64)
    int ix = min(max(__float2int_rd(fmaf(px, s, s)), 0), 63);
    int iy = min(max(__float2int_rd(fmaf(py, s, s)), 0), 63);
    int iz = min(max(__float2int_rd(fmaf(pz, s, s)), 0), 63);
    return expand_bits((unsigned)ix) | (expand_bits((unsigned)iy) << 1)
         | (expand_bits((unsigned)iz) << 2);
}

// ---------------- sorting kernels -------------------------------------------
__global__ void k_zero() {
    d_hist[blockIdx.x * 256u + threadIdx.x] = 0u;
}

__global__ void k_hist(const float* __restrict__ x, int n) {
    int p = blockIdx.x * 256 + threadIdx.x;
    if (p >= n) return;
    float px = x[3 * p], py = x[3 * p + 1], pz = x[3 * p + 2];
    atomicAdd(&d_hist[bucket_key(px, py, pz)], 1u);
}

__global__ void k_scan() {   // single block, 1024 threads, chunk = NB/1024 = 256
    __shared__ unsigned part[1024];
    const int CH = NB / 1024;
    int tid = threadIdx.x;
    unsigned base = tid * CH;
    unsigned s = 0;
    for (int i = 0; i < CH; i++) s += d_hist[base + i];
    part[tid] = s;
    __syncthreads();
    if (tid == 0) {
        unsigned acc = 0;
        for (int i = 0; i < 1024; i++) { unsigned t = part[i]; part[i] = acc; acc += t; }
    }
    __syncthreads();
    unsigned acc = part[tid];
    for (int i = 0; i < CH; i++) {
        unsigned t = d_hist[base + i];
        d_offs[base + i] = acc;
        acc += t;
    }
}

__global__ void k_scatter(const float* __restrict__ x, int n) {
    int p = blockIdx.x * 256 + threadIdx.x;
    if (p >= n) return;
    float px = x[3 * p], py = x[3 * p + 1], pz = x[3 * p + 2];
    unsigned dst = atomicAdd(&d_offs[bucket_key(px, py, pz)], 1u);
    d_xs[dst] = make_float4(px, py, pz, __uint_as_float((unsigned)p));
}

// ---------------- main kernel ------------------------------------------------
// Accumulate all 16 levels in registers (high reg count intentionally caps
// resident blocks at ~3, so 33.8KB smem/block leaves ~127KB of L1D).
// Single end-of-kernel flush writes each point's full 128B output line in one
// warp instruction with .cs (transient L2 residency).
__global__ __launch_bounds__(256) void hash_embed_kernel(
    const ull* __restrict__ tbl,    // tables as (level<<19) float2 entries
    float* __restrict__ out,
    int npts,
    Params prm)
{
    __shared__ float stage[256][33];   // 32 feature floats + orig index

    unsigned i = blockIdx.x * 256u + threadIdx.x;
    int w   = threadIdx.x >> 5;
    int lid = threadIdx.x & 31;

    unsigned p = 0xFFFFFFFFu;
    float px = 0.f, py = 0.f, pz = 0.f;
    if (i < (unsigned)npts) {
        float4 v = d_xs[i];
        px = v.x; py = v.y; pz = v.z;
        p = __float_as_uint(v.w);
    }

    ull acc[16];

#pragma unroll
    for (int l = 0; l < 16; l++) {
        const float ic  = prm.icell[l];
        const float rm1 = prm.resm1[l];

        float ux = fmaf(px, ic, ic);
        float uy = fmaf(py, ic, ic);
        float uz = fmaf(pz, ic, ic);
        float fx = fminf(floorf(ux), rm1);
        float fy = fminf(floorf(uy), rm1);
        float fz = fminf(floorf(uz), rm1);
        float tx = ux - fx;
        float ty = uy - fy;
        float tz = uz - fz;

        unsigned ix0 = (unsigned)fx;
        unsigned iy0 = (unsigned)fy;
        unsigned iz0 = (unsigned)fz;
        unsigned hy0 = iy0 * P1;
        unsigned hy1 = hy0 + P1;
        unsigned hz0 = iz0 * P2;
        unsigned hz1 = hz0 + P2;

        unsigned r00 = hy0 ^ hz0;
        unsigned r10 = hy1 ^ hz0;
        unsigned r01 = hy0 ^ hz1;
        unsigned r11 = hy1 ^ hz1;

        unsigned h00 = (ix0 ^ r00) & MASK;
        unsigned h10 = (ix0 ^ r10) & MASK;
        unsigned h01 = (ix0 ^ r01) & MASK;
        unsigned h11 = (ix0 ^ r11) & MASK;

        const ull* tl = tbl + ((unsigned)l << 19);
        const ulonglong2* tp = (const ulonglong2*)tl;

        // one 16B L1-cached load covers the (ix0, ix0^1) vertex pair
        ulonglong2 q00 = __ldg(tp + (h00 >> 1));
        ulonglong2 q10 = __ldg(tp + (h10 >> 1));
        ulonglong2 q01 = __ldg(tp + (h01 >> 1));
        ulonglong2 q11 = __ldg(tp + (h11 >> 1));

        ull e000 = (h00 & 1) ? q00.y : q00.x;
        ull e010 = (h10 & 1) ? q10.y : q10.x;
        ull e001 = (h01 & 1) ? q01.y : q01.x;
        ull e011 = (h11 & 1) ? q11.y : q11.x;

        ull e100, e110, e101, e111;
        if (ix0 & 1) {
            unsigned ix1 = ix0 + 1u;
            e100 = __ldg(tl + ((ix1 ^ r00) & MASK));
            e110 = __ldg(tl + ((ix1 ^ r10) & MASK));
            e101 = __ldg(tl + ((ix1 ^ r01) & MASK));
            e111 = __ldg(tl + ((ix1 ^ r11) & MASK));
        } else {
            e100 = (h00 & 1) ? q00.x : q00.y;
            e110 = (h10 & 1) ? q10.x : q10.y;
            e101 = (h01 & 1) ? q01.x : q01.y;
            e111 = (h11 & 1) ? q11.x : q11.y;
        }

        ull t2x = pk2(tx, tx);
        ull t2y = pk2(ty, ty);
        ull t2z = pk2(tz, tz);

        ull a0 = lerp2(e000, e100, t2x);
        ull a1 = lerp2(e010, e110, t2x);
        ull a2 = lerp2(e001, e101, t2x);
        ull a3 = lerp2(e011, e111, t2x);
        ull b0 = lerp2(a0, a1, t2y);
        ull b1 = lerp2(a2, a3, t2y);
        acc[l] = lerp2(b0, b1, t2z);
    }

    // single staging pass (conflict-free: pitch 33 words)
#pragma unroll
    for (int l = 0; l < 16; l++) {
        float2 rf = *reinterpret_cast<float2*>(&acc[l]);
        stage[threadIdx.x][2 * l + 0] = rf.x;
        stage[threadIdx.x][2 * l + 1] = rf.y;
    }
    stage[threadIdx.x][32] = __uint_as_float(p);
    __syncwarp();

    // warp-cooperative flush: one full 128B output line per instruction,
    // evict-first so the random-line stream doesn't squat in L2
    for (int j = 0; j < 32; j++) {
        unsigned pj = __float_as_uint(stage[w * 32 + j][32]);
        if (pj == 0xFFFFFFFFu) continue;
        __stcs(out + (ull)pj * 32u + lid, stage[w * 32 + j][lid]);
    }
}

// ---------------- launch ------------------------------------------------------
extern "C" void kernel_launch(void* const* d_in, const int* in_sizes, int n_in,
                              void* d_out, int out_size) {
    int xi = 0, ti = 1;
    if (n_in >= 2 && in_sizes[0] > in_sizes[1]) { xi = 1; ti = 0; }

    const float* x = (const float*)d_in[xi];
    const ull* tbl = (const ull*)d_in[ti];
    float* out = (float*)d_out;

    Params prm;
    double factor = exp((log(512.0) - log(16.0)) / 15.0);
    for (int i = 0; i < 16; i++) {
        double r = floor(16.0 * pow(factor, (double)i));
        prm.icell[i] = (float)(r * 0.5);
        prm.resm1[i] = (float)(r - 1.0);
    }

    int npts = in_sizes[xi] / 3;
    int pb = (npts + 255) / 256;

    k_zero<<<NB / 256, 256>>>();
    k_hist<<<pb, 256>>>(x, npts);
    k_scan<<<1, 1024>>>();
    k_scatter<<<pb, 256>>>(x, npts);
    hash_embed_kernel<<<pb, 256>>>(tbl, out, npts, prm);
}